// round 17
// baseline (speedup 1.0000x reference)
#include <cuda_runtime.h>
#include <cuda_fp16.h>
#include <math.h>
#include <stdint.h>

#define BB 4
#define CC 32
#define NHEAD 4
#define HDIM 8
#define NN 32768
#define PP 64
#define KSPLIT 128

#define PADN   39304            // 34*34*34
#define GUARD  1536
#define PADSTR (PADN + 2*GUARD) // rows per batch
#define NTILE2 146              // tokens [1024, 38400) in 256-token blocks

// ---------------- scratch (static device memory; no allocations) ----------------
static __device__ float g_xt  [BB*NN*CC];
static __device__ float g_part[(size_t)KSPLIT*256*64];   // split-K partials
static __device__ float g_kproj[BB*CC*PP];
static __device__ float g_vproj[BB*CC*PP];
static __device__ float g_npart[8*16*80];
static __device__ float g_qinv[BB*CC];
static __device__ float g_attnca[BB*NHEAD*HDIM*HDIM];
static __device__ float g_skip[BB*CC*NN];      // [b][c][n] for k_final
static __device__ float g_skiptm[BB*NN*CC];    // [b][n][c] for conv2 residual
static __device__ float g_y2tm [BB*NN*CC];     // [b][n][c] conv2 output
// fp16 attention tensors (gamma-damped branch)
static __device__ __align__(16) __half g_q16 [(size_t)16*NN*8];  // [b*4+h][n][d]
static __device__ __align__(16) __half g_k16 [(size_t)16*NN*8];  // [b*4+h][n][d]
static __device__ __align__(16) __half g_vca16[(size_t)16*NN*8]; // [b*4+h][n][d]
static __device__ __align__(16) __half g_kv16[(size_t)256*NN];   // rows 0-127 k, 128-255 v_sa
static __device__ __align__(16) __half g_ef16[(size_t)PP*NN];
static __device__ __align__(16) __half g_xsa16[(size_t)128*NN];  // [bh*8+d][n]
static __device__ __align__(16) __half g_xca16[(size_t)128*NN];  // [b*32+c][n]
static __device__ __align__(16) __half g_wq16[128*32];           // [col][k] fp16 W image
// padded token-major conv activations: [b][padtoken][32 fp16]
static __device__ __align__(16) __half g_pad1[(size_t)BB*PADSTR*32];
static __device__ __align__(16) __half g_pad2[(size_t)BB*PADSTR*32];
// weight images: [tap][co(32)][ci(32)] fp16
static __device__ __align__(16) __half g_wimg1[27*32*32];
static __device__ __align__(16) __half g_wimg2[27*32*32];

// ---------------- helpers ----------------
#define SW64(o)  ((o) ^ (((o) >> 3) & 0x30))
#define SW128(o) ((o) ^ (((o) >> 3) & 0x70))

__device__ __forceinline__ uint32_t smem_u32(const void* p) {
    uint32_t a;
    asm("{ .reg .u64 t; cvta.to.shared.u64 t, %1; cvt.u32.u64 %0, t; }" : "=r"(a) : "l"(p));
    return a;
}
__device__ __forceinline__ void ldmx4(uint32_t* r, uint32_t addr) {
    asm volatile("ldmatrix.sync.aligned.m8n8.x4.shared.b16 {%0,%1,%2,%3}, [%4];"
                 : "=r"(r[0]), "=r"(r[1]), "=r"(r[2]), "=r"(r[3]) : "r"(addr));
}
__device__ __forceinline__ void mma_fp16(float* d, const uint32_t* a, uint32_t b0, uint32_t b1) {
    asm volatile("mma.sync.aligned.m16n8k16.row.col.f32.f16.f16.f32 "
                 "{%0,%1,%2,%3}, {%4,%5,%6,%7}, {%8,%9}, {%0,%1,%2,%3};"
                 : "+f"(d[0]), "+f"(d[1]), "+f"(d[2]), "+f"(d[3])
                 : "r"(a[0]), "r"(a[1]), "r"(a[2]), "r"(a[3]), "r"(b0), "r"(b1));
}

// ---------------- Wq fp16 transpose prep: g_wq16[col][k] ----------------
__global__ __launch_bounds__(256) void k_wq_prep(const float* __restrict__ Wq)
{
    int id = blockIdx.x*256 + threadIdx.x;     // 0..4095
    if (id >= 4096) return;
    int col = id >> 5, k = id & 31;
    g_wq16[id] = __float2half_rn(Wq[k*128 + col]);
}

// ---------------- K1 v2: transpose+pos, layernorm, QKVV GEMM via mma ----------------
// Block = 128 tokens, 256 threads (8 warps). GEMM: M=128 tok, N=128 cols, K=32.
__global__ __launch_bounds__(256) void k1_tok_ln_qkvv(
    const float* __restrict__ x, const float* __restrict__ pos,
    const float* __restrict__ lng, const float* __restrict__ lnb)
{
    __shared__ __align__(16) char sbuf[33280];
    float (*xts)[33]  = reinterpret_cast<float(*)[33]>(sbuf);          // 16896B
    __half (*ktr)[132] = reinterpret_cast<__half(*)[132]>(sbuf);       // overlay (after LN)
    __half* Asm = reinterpret_cast<__half*>(sbuf + 16896);             // [128][32] SW64, 8KB
    __half* Bsm = reinterpret_cast<__half*>(sbuf + 16896 + 8192);      // [128][32] SW64, 8KB

    int b  = blockIdx.x >> 8;
    int n0 = (blockIdx.x & 255) << 7;
    int t  = threadIdx.x;
    int warp = t >> 5, lane = t & 31;

    // stage W (fp16 [col][k]) -> Bsm swizzled
    for (int i = t; i < 512; i += 256) {
        int row = i >> 2, cq = i & 3;
        float4 v = *reinterpret_cast<const float4*>(g_wq16 + row*32 + cq*8);
        *reinterpret_cast<float4*>(reinterpret_cast<char*>(Bsm) + SW64(row*64 + cq*16)) = v;
    }
    // load x tile (coalesced along n)
    for (int i = t; i < 4096; i += 256) {
        int c = i >> 7, j = i & 127;
        xts[j][c] = x[(b*CC + c)*NN + n0 + j];
    }
    __syncthreads();
    // pos add + xt write (coalesced along c)
    for (int i = t; i < 4096; i += 256) {
        int j = i >> 5, c = i & 31;
        float v = xts[j][c] + pos[(n0 + j)*CC + c];
        xts[j][c] = v;
        g_xt[(b*NN + n0 + j)*CC + c] = v;
    }
    __syncthreads();
    // layernorm: warp w handles tokens 16w..16w+15, lane = channel; write Asm fp16
    for (int jj = 0; jj < 16; jj++) {
        int j = warp*16 + jj;
        float v = xts[j][lane];
        float s = v, ss = v*v;
        #pragma unroll
        for (int o = 16; o > 0; o >>= 1) {
            s  += __shfl_xor_sync(0xffffffffu, s, o);
            ss += __shfl_xor_sync(0xffffffffu, ss, o);
        }
        float mu  = s * (1.0f/32.0f);
        float var = ss * (1.0f/32.0f) - mu*mu;
        float r   = rsqrtf(var + 1e-5f);
        float xn  = (v - mu) * r * lng[lane] + lnb[lane];
        *reinterpret_cast<__half*>(
            reinterpret_cast<char*>(Asm) + SW64(j*64 + lane*2)) = __float2half_rn(xn);
    }
    __syncthreads();

    // mma: warp -> M-tile 16 tokens, all 128 cols
    uint32_t Abase = smem_u32(Asm), Bbase = smem_u32(Bsm);
    int a_rl = (lane & 7) + ((lane >> 3) & 1)*8;
    int a_cs = lane >> 4;
    int b_rn = (lane & 7) + ((lane >> 4) << 3);
    int b_cs = (lane >> 3) & 1;

    float acc[16][4];
    #pragma unroll
    for (int nb = 0; nb < 16; nb++)
        #pragma unroll
        for (int j = 0; j < 4; j++) acc[nb][j] = 0.f;

    #pragma unroll
    for (int ks = 0; ks < 2; ks++) {
        uint32_t a[4];
        int row = warp*16 + a_rl;
        ldmx4(a, Abase + SW64(row*64 + (2*ks + a_cs)*16));
        #pragma unroll
        for (int np = 0; np < 8; np++) {
            uint32_t bf[4];
            int rn = np*16 + b_rn;
            ldmx4(bf, Bbase + SW64(rn*64 + (2*ks + b_cs)*16));
            mma_fp16(acc[np*2],     a, bf[0], bf[1]);
            mma_fp16(acc[np*2 + 1], a, bf[2], bf[3]);
        }
    }

    // epilogue: direct q/k/vca stores + ktr staging for kv16 (k + v_sa)
    int cl = lane & 3;
    #pragma unroll
    for (int nb = 0; nb < 16; nb++) {
        int which = nb >> 2;          // 0=q,1=k,2=vca,3=vsa
        int hh    = nb & 3;
        #pragma unroll
        for (int half = 0; half < 2; half++) {
            int m = warp*16 + (lane >> 2) + half*8;
            float v0 = acc[nb][half*2], v1 = acc[nb][half*2 + 1];
            __half h0 = __float2half_rn(v0), h1 = __float2half_rn(v1);
            if (which < 3) {
                __half* basep = (which == 0) ? g_q16 : (which == 1) ? g_k16 : g_vca16;
                *reinterpret_cast<__half2*>(
                    basep + ((size_t)(b*4 + hh)*NN + n0 + m)*8 + 2*cl) = __half2(h0, h1);
            }
            if (which == 1) {               // k -> ktr rows 0..31
                int c = hh*8 + 2*cl;
                ktr[c][m] = h0; ktr[c + 1][m] = h1;
            } else if (which == 3) {        // vsa -> ktr rows 32..63
                int c = 32 + hh*8 + 2*cl;
                ktr[c][m] = h0; ktr[c + 1][m] = h1;
            }
        }
    }
    __syncthreads();
    // coalesced kv16 stores
    for (int i = t; i < 64*64; i += 256) {
        int r = i >> 6, mp = i & 63;
        __half2 v = __half2(ktr[r][2*mp], ktr[r][2*mp + 1]);
        int dstrow = (r < 32) ? (b*32 + r) : (128 + b*32 + (r - 32));
        *reinterpret_cast<__half2*>(g_kv16 + (size_t)dstrow*NN + n0 + 2*mp) = v;
    }
}

// ---------------- EF weight fp16 prep ----------------
__global__ __launch_bounds__(256) void k_ef_prep(const float* __restrict__ EFw)
{
    int i = blockIdx.x*256 + threadIdx.x;   // over 2M/4 float4s
    float4 v = *reinterpret_cast<const float4*>(EFw + (size_t)i*4);
    __half2 h[2];
    h[0] = __half2(__float2half_rn(v.x), __float2half_rn(v.y));
    h[1] = __half2(__float2half_rn(v.z), __float2half_rn(v.w));
    *reinterpret_cast<uint2*>(g_ef16 + (size_t)i*4) = *reinterpret_cast<uint2*>(h);
}

// ---------------- K2: EF projections via fp16 mma (split-K) ----------------
__global__ __launch_bounds__(256) void k2_mma()
{
    __shared__ __align__(128) __half Asm[128*64];   // 16 KB
    __shared__ __align__(128) __half Bsm[64*64];    // 8 KB
    int t = threadIdx.x, warp = t >> 5, lane = t & 31;
    int split = blockIdx.x, rg = blockIdx.y;
    const __half* gA = g_kv16 + (size_t)rg*128*NN;
    int nb0 = split*256;

    uint32_t Abase = smem_u32(Asm), Bbase = smem_u32(Bsm);
    float acc[8][4];
    #pragma unroll
    for (int nb = 0; nb < 8; nb++)
        #pragma unroll
        for (int j = 0; j < 4; j++) acc[nb][j] = 0.f;

    int a_rl = (lane & 7) + ((lane >> 3) & 1)*8;
    int a_cs = lane >> 4;
    int b_rn = (lane & 7) + ((lane >> 4) << 3);
    int b_cs = (lane >> 3) & 1;

    for (int st = 0; st < 4; st++) {
        int nb = nb0 + st*64;
        __syncthreads();
        for (int idx = t; idx < 1024; idx += 256) {
            int r = idx >> 3, c = idx & 7;
            float4 v = *reinterpret_cast<const float4*>(gA + (size_t)r*NN + nb + c*8);
            *reinterpret_cast<float4*>(
                reinterpret_cast<char*>(Asm) + SW128(r*128 + c*16)) = v;
        }
        for (int idx = t; idx < 512; idx += 256) {
            int r = idx >> 3, c = idx & 7;
            float4 v = *reinterpret_cast<const float4*>(g_ef16 + (size_t)r*NN + nb + c*8);
            *reinterpret_cast<float4*>(
                reinterpret_cast<char*>(Bsm) + SW128(r*128 + c*16)) = v;
        }
        __syncthreads();
        #pragma unroll
        for (int ks = 0; ks < 4; ks++) {
            uint32_t a[4];
            int row = warp*16 + a_rl;
            ldmx4(a, Abase + SW128(row*128 + (2*ks + a_cs)*16));
            uint32_t bf[16];
            #pragma unroll
            for (int np = 0; np < 4; np++) {
                int rn = np*16 + b_rn;
                ldmx4(&bf[np*4], Bbase + SW128(rn*128 + (2*ks + b_cs)*16));
            }
            #pragma unroll
            for (int nb2 = 0; nb2 < 8; nb2++) {
                int bi = (nb2 >> 1)*4 + (nb2 & 1)*2;
                mma_fp16(acc[nb2], a, bf[bi], bf[bi + 1]);
            }
        }
    }
    int rbase = rg*128 + warp*16;
    #pragma unroll
    for (int nb2 = 0; nb2 < 8; nb2++) {
        int col = nb2*8 + 2*(lane & 3);
        #pragma unroll
        for (int half = 0; half < 2; half++) {
            int row = rbase + (lane >> 2) + half*8;
            *reinterpret_cast<float2*>(&g_part[((size_t)split*256 + row)*64 + col]) =
                make_float2(acc[nb2][half*2], acc[nb2][half*2 + 1]);
        }
    }
}

__global__ __launch_bounds__(256) void k2_proj_reduce(const float* __restrict__ EFb)
{
    int idx = blockIdx.x * 256 + threadIdx.x;   // 0..16383
    int row = idx >> 6, p = idx & 63;
    float s = 0.f;
    for (int c = 0; c < KSPLIT; c++) s += g_part[((size_t)c*256 + row)*64 + p];
    s += EFb[p];
    if (row < 128) g_kproj[row*PP + p] = s;
    else           g_vproj[(row - 128)*PP + p] = s;
}

// ---------------- K3a: gram matrix + L2 norms (fp16 inputs) ----------------
__global__ __launch_bounds__(256) void k3a_gram_partial()
{
    int split = blockIdx.x;
    int bh    = blockIdx.y;
    int t     = threadIdx.x;
    const __half* qb = g_q16 + (size_t)bh*NN*8;
    const __half* kb = g_k16 + (size_t)bh*NN*8;

    float v[80];
    #pragma unroll
    for (int i = 0; i < 80; i++) v[i] = 0.f;

    int nend = split*4096 + 4096;
    for (int n = split*4096 + t; n < nend; n += 256) {
        uint4 qu = *reinterpret_cast<const uint4*>(qb + (size_t)n*8);
        uint4 ku = *reinterpret_cast<const uint4*>(kb + (size_t)n*8);
        const __half2* qh = reinterpret_cast<const __half2*>(&qu);
        const __half2* kh = reinterpret_cast<const __half2*>(&ku);
        float qv[8], kv[8];
        #pragma unroll
        for (int j = 0; j < 4; j++) {
            float2 fq = __half22float2(qh[j]);
            float2 fk = __half22float2(kh[j]);
            qv[2*j] = fq.x; qv[2*j + 1] = fq.y;
            kv[2*j] = fk.x; kv[2*j + 1] = fk.y;
        }
        #pragma unroll
        for (int d = 0; d < 8; d++) {
            v[64 + d] += qv[d]*qv[d];
            v[72 + d] += kv[d]*kv[d];
            #pragma unroll
            for (int e = 0; e < 8; e++) v[d*8 + e] += qv[d]*kv[e];
        }
    }
    __shared__ float wsum[8][80];
    int w = t >> 5, lane = t & 31;
    #pragma unroll
    for (int i = 0; i < 80; i++) {
        float s = v[i];
        #pragma unroll
        for (int o = 16; o > 0; o >>= 1) s += __shfl_xor_sync(0xffffffffu, s, o);
        if (lane == 0) wsum[w][i] = s;
    }
    __syncthreads();
    if (t < 80) {
        float s = 0.f;
        #pragma unroll
        for (int ww = 0; ww < 8; ww++) s += wsum[ww][t];
        g_npart[(split*16 + bh)*80 + t] = s;
    }
}

__global__ __launch_bounds__(128) void k3a_finalize(const float* __restrict__ temp1)
{
    int bh = blockIdx.x;
    int t  = threadIdx.x;
    __shared__ float tot[80];
    __shared__ float qi[8], ki[8];
    if (t < 80) {
        float s = 0.f;
        #pragma unroll
        for (int sp = 0; sp < 8; sp++) s += g_npart[(sp*16 + bh)*80 + t];
        tot[t] = s;
    }
    __syncthreads();
    if (t < 8) {
        float qn = sqrtf(tot[64 + t]);
        float kn = sqrtf(tot[72 + t]);
        qi[t] = 1.0f / fmaxf(qn, 1e-12f);
        ki[t] = 1.0f / fmaxf(kn, 1e-12f);
        g_qinv[bh*8 + t] = qi[t];
    }
    __syncthreads();
    if (t < 8) {
        int h = bh & 3;
        float t1 = temp1[h];
        float sc[8];
        float m = -1e30f;
        #pragma unroll
        for (int e = 0; e < 8; e++) {
            sc[e] = tot[t*8 + e] * qi[t] * ki[e] * t1;
            m = fmaxf(m, sc[e]);
        }
        float sum = 0.f;
        #pragma unroll
        for (int e = 0; e < 8; e++) { sc[e] = __expf(sc[e] - m); sum += sc[e]; }
        float inv = 1.0f / sum;
        #pragma unroll
        for (int e = 0; e < 8; e++) g_attnca[bh*64 + t*8 + e] = sc[e]*inv;
    }
}

// ---------------- K3b: spatial attention + channel-attn apply (half2 math) ----------------
__global__ __launch_bounds__(128) void k3b_attn(const float* __restrict__ temp2)
{
    int bh = blockIdx.y;
    int n  = blockIdx.x * 128 + threadIdx.x;
    int h  = bh & 3;
    int t  = threadIdx.x;
    __shared__ __half2 kq2[8][32], vp2[8][32];
    __shared__ float A[8][8];
    float t2 = temp2[h];
    for (int i = t; i < 256; i += 128) {
        int d = i >> 5, pp = i & 31;
        float qinv = g_qinv[bh*8 + d];
        float2 kp = *reinterpret_cast<const float2*>(&g_kproj[(bh*8 + d)*PP + 2*pp]);
        float2 vp = *reinterpret_cast<const float2*>(&g_vproj[(bh*8 + d)*PP + 2*pp]);
        kq2[d][pp] = __floats2half2_rn(qinv*kp.x*t2, qinv*kp.y*t2);
        vp2[d][pp] = __floats2half2_rn(vp.x, vp.y);
    }
    if (t < 64) A[t >> 3][t & 7] = g_attnca[bh*64 + t];
    __syncthreads();

    uint4 qu = *reinterpret_cast<const uint4*>(g_q16 + ((size_t)bh*NN + n)*8);
    const __half* qh = reinterpret_cast<const __half*>(&qu);
    __half2 qv2[8];
    #pragma unroll
    for (int d = 0; d < 8; d++) qv2[d] = __half2half2(qh[d]);

    __half2 s2[32];
    #pragma unroll
    for (int pp = 0; pp < 32; pp++) s2[pp] = __hmul2(qv2[0], kq2[0][pp]);
    #pragma unroll
    for (int d = 1; d < 8; d++)
        #pragma unroll
        for (int pp = 0; pp < 32; pp++) s2[pp] = __hfma2(qv2[d], kq2[d][pp], s2[pp]);

    float s[64];
    #pragma unroll
    for (int pp = 0; pp < 32; pp++) {
        float2 f = __half22float2(s2[pp]);
        s[2*pp] = f.x; s[2*pp + 1] = f.y;
    }
    float m = s[0];
    #pragma unroll
    for (int p = 1; p < 64; p++) m = fmaxf(m, s[p]);
    float sum = 0.f;
    #pragma unroll
    for (int p = 0; p < 64; p++) { s[p] = __expf(s[p] - m); sum += s[p]; }
    float inv = 1.0f / sum;

    __half2 w2[32];
    #pragma unroll
    for (int pp = 0; pp < 32; pp++)
        w2[pp] = __floats2half2_rn(s[2*pp]*inv, s[2*pp + 1]*inv);

    #pragma unroll
    for (int d = 0; d < 8; d++) {
        __half2 o2 = __hmul2(w2[0], vp2[d][0]);
        #pragma unroll
        for (int pp = 1; pp < 32; pp++) o2 = __hfma2(w2[pp], vp2[d][pp], o2);
        float2 f = __half22float2(o2);
        g_xsa16[(size_t)(bh*8 + d)*NN + n] = __float2half_rn(f.x + f.y);
    }
    uint4 vu = *reinterpret_cast<const uint4*>(g_vca16 + ((size_t)bh*NN + n)*8);
    const __half2* vh = reinterpret_cast<const __half2*>(&vu);
    float vv[8];
    #pragma unroll
    for (int j = 0; j < 4; j++) {
        float2 f = __half22float2(vh[j]);
        vv[2*j] = f.x; vv[2*j + 1] = f.y;
    }
    #pragma unroll
    for (int d = 0; d < 8; d++) {
        float xc = 0.f;
        #pragma unroll
        for (int e = 0; e < 8; e++) xc += A[d][e]*vv[e];
        g_xca16[(size_t)(bh*8 + d)*NN + n] = __float2half_rn(xc);
    }
}

// ---------------- K4: combine; write skip ([c][n] and [n][c]) + pad1 (fp16) ----------------
__global__ __launch_bounds__(128) void k4_combine(
    const float* __restrict__ o1w, const float* __restrict__ o1b,
    const float* __restrict__ o2w, const float* __restrict__ o2b,
    const float* __restrict__ gamma)
{
    __shared__ float sa[32][33], ca[32][33], xtl[32][33], resm[32][33];
    __shared__ float w1[16][32], w2[16][32], b1[16], b2[16], gm[32];
    int b  = blockIdx.x >> 10;
    int t0 = (blockIdx.x & 1023) << 5;
    int t  = threadIdx.x;
    int dd   = t0 >> 12;
    int hh   = (t0 >> 10) & 3;
    int nsrc = (t0 & 1023) << 5;

    const __half* sap = g_xsa16 + (size_t)((b*4 + hh)*8 + dd)*NN + nsrc;
    for (int i = t; i < 1024; i += 128) sa[i >> 5][i & 31] = __half2float(sap[i]);
    for (int i = t; i < 1024; i += 128) {
        int c = i >> 5, ii = i & 31;
        ca[ii][c] = __half2float(g_xca16[(size_t)(b*CC + c)*NN + t0 + ii]);
    }
    for (int i = t; i < 1024; i += 128) {
        int ii = i >> 5, c = i & 31;
        xtl[ii][c] = g_xt[(b*NN + t0 + ii)*CC + c];
    }
    for (int i = t; i < 512; i += 128) {
        w1[i >> 5][i & 31] = o1w[i];
        w2[i >> 5][i & 31] = o2w[i];
    }
    if (t < 16) { b1[t] = o1b[t]; b2[t] = o2b[t]; }
    if (t < 32) gm[t] = gamma[t];
    __syncthreads();

    int ii = t & 31;
    int cg = t >> 5;
    #pragma unroll
    for (int cc = 0; cc < 8; cc++) {
        int c = cg*8 + cc;
        float val;
        if (c < 16) {
            float s = b1[c];
            #pragma unroll
            for (int k = 0; k < 32; k++) s += sa[ii][k]*w1[c][k];
            val = s;
        } else {
            int j = c - 16;
            float s = b2[j];
            #pragma unroll
            for (int k = 0; k < 32; k++) s += ca[ii][k]*w2[j][k];
            val = s;
        }
        float r = xtl[ii][c] + gm[c]*val;
        resm[ii][c] = r;
        g_skip[(b*CC + c)*NN + t0 + ii] = r;
    }
    __syncthreads();
    int tok = t >> 2, cgp = t & 3;
    int n   = t0 + tok;
    {
        float4 v0 = make_float4(resm[tok][cgp*8],   resm[tok][cgp*8+1],
                                resm[tok][cgp*8+2], resm[tok][cgp*8+3]);
        float4 v1 = make_float4(resm[tok][cgp*8+4], resm[tok][cgp*8+5],
                                resm[tok][cgp*8+6], resm[tok][cgp*8+7]);
        float4* d = reinterpret_cast<float4*>(g_skiptm + ((size_t)b*NN + n)*CC + cgp*8);
        d[0] = v0; d[1] = v1;
    }
    int npad = ((n >> 10) + 1)*1156 + (((n >> 5) & 31) + 1)*34 + (n & 31) + 1;
    __half2 h[4];
    #pragma unroll
    for (int j = 0; j < 4; j++)
        h[j] = __half2(__float2half_rn(resm[tok][cgp*8 + 2*j]),
                       __float2half_rn(resm[tok][cgp*8 + 2*j + 1]));
    *reinterpret_cast<uint4*>(g_pad1 + ((size_t)b*PADSTR + GUARD + npad)*32 + cgp*8) =
        *reinterpret_cast<uint4*>(h);
}

// ---------------- weight prep: fp16 images [tap][co][ci] ----------------
__global__ __launch_bounds__(256) void kw_prep(const float* __restrict__ w, int which)
{
    int j = blockIdx.x*256 + threadIdx.x;      // 0 .. 27648
    if (j >= 27648) return;
    __half* out = which ? g_wimg2 : g_wimg1;
    int tap = j % 27; int r = j / 27; int ci = r & 31; int co = r >> 5;
    out[(tap*32 + co)*32 + ci] = __float2half_rn(w[j]);
}

// ---------------- conv via mma.sync: single-chain fp16, K=32, 64B rows ----------------
template<int MODE>
__global__ __launch_bounds__(256) void conv_mma(
    const float* __restrict__ cb, const float* __restrict__ bg,
    const float* __restrict__ bb, const float* __restrict__ bm,
    const float* __restrict__ bv)
{
    __shared__ __align__(128) __half Asm[258*32];   // 16.5 KB
    __shared__ __align__(128) __half Bsm[3*32*32];  // 6 KB
    __shared__ float scs[32], bss[32];

    const __half* gA = (MODE == 1) ? g_pad1 : g_pad2;
    const __half* gW = (MODE == 1) ? g_wimg1 : g_wimg2;

    int t = threadIdx.x, warp = t >> 5, lane = t & 31;
    int base = 1024 + blockIdx.x * 256;
    int b    = blockIdx.y;
    long volr = (long)b*PADSTR + GUARD;

    if (t < 32) {
        float a = bg[t]*rsqrtf(bv[t] + 1e-5f);
        scs[t] = a;
        bss[t] = (cb[t] - bm[t])*a + bb[t];
    }

    uint32_t Abase = smem_u32(Asm), Bbase = smem_u32(Bsm);
    float acc[2][4][4];
    #pragma unroll
    for (int mt = 0; mt < 2; mt++)
        #pragma unroll
        for (int nb = 0; nb < 4; nb++)
            #pragma unroll
            for (int j = 0; j < 4; j++) acc[mt][nb][j] = 0.f;

    int a_rl = (lane & 7) + ((lane >> 3) & 1)*8;
    int a_cs = lane >> 4;
    int b_rn = (lane & 7) + ((lane >> 4) << 3);
    int b_cs = (lane >> 3) & 1;

    for (int kzy = 0; kzy < 9; kzy++) {
        int kz = kzy/3, ky = kzy - kz*3;
        __syncthreads();
        long rowb = volr + base + (kz - 1)*1156 + (ky - 1)*34 - 1;
        for (int idx = t; idx < 1032; idx += 256) {
            int r = idx >> 2, c = idx & 3;
            float4 v = *reinterpret_cast<const float4*>(gA + (rowb + r)*32 + c*8);
            *reinterpret_cast<float4*>(
                reinterpret_cast<char*>(Asm) + SW64(r*64 + c*16)) = v;
        }
        for (int idx = t; idx < 384; idx += 256) {
            int row = idx >> 2, c = idx & 3;
            int dx = row >> 5, co = row & 31;
            float4 v = *reinterpret_cast<const float4*>(
                gW + ((size_t)(kzy*3 + dx)*32 + co)*32 + c*8);
            *reinterpret_cast<float4*>(
                reinterpret_cast<char*>(Bsm) + dx*2048 + SW64(co*64 + c*16)) = v;
        }
        __syncthreads();
        #pragma unroll
        for (int dx = 0; dx < 3; dx++) {
            #pragma unroll
            for (int ks = 0; ks < 2; ks++) {
                uint32_t a[2][4];
                #pragma unroll
                for (int mt = 0; mt < 2; mt++) {
                    int row = warp*32 + mt*16 + a_rl + dx;
                    ldmx4(a[mt], Abase + SW64(row*64 + (2*ks + a_cs)*16));
                }
                uint32_t bf[8];
                #pragma unroll
                for (int np = 0; np < 2; np++) {
                    int rn = np*16 + b_rn;
                    ldmx4(&bf[np*4],
                          Bbase + dx*2048 + SW64(rn*64 + (2*ks + b_cs)*16));
                }
                #pragma unroll
                for (int mt = 0; mt < 2; mt++)
                    #pragma unroll
                    for (int nb = 0; nb < 4; nb++) {
                        int bi = (nb >> 1)*4 + (nb & 1)*2;
                        mma_fp16(acc[mt][nb], a[mt], bf[bi], bf[bi + 1]);
                    }
            }
        }
    }

    int cl = lane & 3;
    #pragma unroll
    for (int mt = 0; mt < 2; mt++)
        #pragma unroll
        for (int half = 0; half < 2; half++) {
            int m = base + warp*32 + mt*16 + (lane >> 2) + half*8;
            int zp = m / 1156; int rem = m - zp*1156;
            int yp = rem / 34; int xp = rem - yp*34;
            if (zp < 1 || zp > 32 || yp < 1 || yp > 32 || xp < 1 || xp > 32) continue;
            if (MODE == 1) {
                __half* dst = g_pad2 + (volr + m)*32;
                #pragma unroll
                for (int nb = 0; nb < 4; nb++) {
                    int co = nb*8 + 2*cl;
                    float v0 = acc[mt][nb][half*2]    *scs[co]   + bss[co];
                    float v1 = acc[mt][nb][half*2 + 1]*scs[co+1] + bss[co+1];
                    v0 = (v0 > 0.f) ? v0 : 0.01f*v0;
                    v1 = (v1 > 0.f) ? v1 : 0.01f*v1;
                    *reinterpret_cast<__half2*>(dst + co) =
                        __half2(__float2half_rn(v0), __float2half_rn(v1));
                }
            } else {
                int n = (zp - 1)*1024 + (yp - 1)*32 + (xp - 1);
                const float* sk = g_skiptm + ((size_t)b*NN + n)*CC;
                float* dst = g_y2tm + ((size_t)b*NN + n)*CC;
                #pragma unroll
                for (int nb = 0; nb < 4; nb++) {
                    int co = nb*8 + 2*cl;
                    float2 s = *reinterpret_cast<const float2*>(sk + co);
                    float v0 = acc[mt][nb][half*2]    *scs[co]   + bss[co]   + s.x;
                    float v1 = acc[mt][nb][half*2 + 1]*scs[co+1] + bss[co+1] + s.y;
                    v0 = (v0 > 0.f) ? v0 : 0.01f*v0;
                    v1 = (v1 > 0.f) ? v1 : 0.01f*v1;
                    *reinterpret_cast<float2*>(dst + co) = make_float2(v0, v1);
                }
            }
        }
}

// ---------------- final: 1x1 conv residual (reads token-major y2) ----------------
__global__ __launch_bounds__(256) void k_final(
    const float* __restrict__ wp, const float* __restrict__ bp,
    float* __restrict__ outp)
{
    __shared__ float ys[64][33];
    __shared__ float wsm[32][32];
    __shared__ float bsh[32];
    int b  = blockIdx.x >> 9;
    int n0 = (blockIdx.x & 511) << 6;
    int t  = threadIdx.x;
    for (int i = t; i < 2048; i += 256) {
        int nn = i >> 5, ci = i & 31;
        ys[nn][ci] = g_y2tm[((size_t)b*NN + n0 + nn)*CC + ci];
    }
    for (int i = t; i < 1024; i += 256) wsm[i >> 5][i & 31] = wp[i];
    if (t < 32) bsh[t] = bp[t];
    __syncthreads();
    int nn = t & 63;
    int cg = t >> 6;
    #pragma unroll
    for (int cc = 0; cc < 8; cc++) {
        int co = cg*8 + cc;
        float s = bsh[co];
        #pragma unroll
        for (int ci = 0; ci < 32; ci++) s += wsm[co][ci]*ys[nn][ci];
        int idx = (b*32 + co)*NN + n0 + nn;
        outp[idx] = g_skip[idx] + s;
    }
}

// ---------------- launch ----------------
extern "C" void kernel_launch(void* const* d_in, const int* in_sizes, int n_in,
                              void* d_out, int out_size)
{
    const float* x    = (const float*)d_in[0];
    const float* pos  = (const float*)d_in[1];
    const float* lng  = (const float*)d_in[2];
    const float* lnb  = (const float*)d_in[3];
    const float* gam  = (const float*)d_in[4];
    const float* Wq   = (const float*)d_in[5];
    const float* EFw  = (const float*)d_in[6];
    const float* EFb  = (const float*)d_in[7];
    const float* t1   = (const float*)d_in[8];
    const float* t2   = (const float*)d_in[9];
    const float* o1w  = (const float*)d_in[10];
    const float* o1b  = (const float*)d_in[11];
    const float* o2w  = (const float*)d_in[12];
    const float* o2b  = (const float*)d_in[13];
    const float* c1w  = (const float*)d_in[14];
    const float* c1b  = (const float*)d_in[15];
    const float* b1g  = (const float*)d_in[16];
    const float* b1b  = (const float*)d_in[17];
    const float* b1m  = (const float*)d_in[18];
    const float* b1v  = (const float*)d_in[19];
    const float* c2w  = (const float*)d_in[20];
    const float* c2b  = (const float*)d_in[21];
    const float* b2g  = (const float*)d_in[22];
    const float* b2b  = (const float*)d_in[23];
    const float* b2m  = (const float*)d_in[24];
    const float* b2v  = (const float*)d_in[25];
    const float* cpw  = (const float*)d_in[26];
    const float* cpb  = (const float*)d_in[27];
    float* outp = (float*)d_out;

    // launch index 3 = new k1 (profiled this round)
    k_wq_prep<<<16, 256>>>(Wq);                                    // 0
    k_ef_prep<<<2048, 256>>>(EFw);                                 // 1
    kw_prep<<<108, 256>>>(c1w, 0);                                 // 2
    k1_tok_ln_qkvv<<<1024, 256>>>(x, pos, lng, lnb);              // 3  <- profiled
    k3a_gram_partial<<<dim3(8, 16), 256>>>();                      // 4
    k2_mma<<<dim3(KSPLIT, 2), 256>>>();                            // 5
    k2_proj_reduce<<<64, 256>>>(EFb);                              // 6
    k3a_finalize<<<16, 128>>>(t1);                                 // 7
    kw_prep<<<108, 256>>>(c2w, 1);                                 // 8
    k3b_attn<<<dim3(256, 16), 128>>>(t2);                          // 9
    k4_combine<<<4096, 128>>>(o1w, o1b, o2w, o2b, gam);            // 10
    conv_mma<1><<<dim3(NTILE2, BB), 256>>>(c1b, b1g, b1b, b1m, b1v);
    conv_mma<2><<<dim3(NTILE2, BB), 256>>>(c2b, b2g, b2b, b2m, b2v);
    k_final<<<2048, 256>>>(cpw, cpb, outp);
}